// round 13
// baseline (speedup 1.0000x reference)
#include <cuda_runtime.h>
#include <cstdint>

// Problem shape (fixed by dataset): B=2, S=2048, A=16, H=1024, NH=16, HD=64
#define BB 2
#define SS 2048
#define AA 16
#define HH 1024
#define NH 16
#define HD 64
#define NBLK 512

// ---- scratch (device globals; no allocation allowed) ----
__device__ __align__(16) float g_q[BB * HH];           // q[b, o]
__device__ __align__(16) float g_v[BB * NH * HH];      // folded key weights v[b, h, i]
__device__ __align__(16) float g_e[BB * NH * SS];      // e[b,h,k] = masked exp(score)
__device__ __align__(16) float g_z[BB * NH];           // per-(b,h) sum of e
__device__ unsigned int g_bar[4];                      // monotonic grid-barrier counters

// ---- mask dtype detection (sentence_mask[0][0..3] always true since len >= S/2) ----
__device__ __forceinline__ int detect_mode(const void* sm) {
    unsigned int w0 = *(const unsigned int*)sm;
    if (w0 == 0x01010101u) return 1;   // 1-byte bool
    if (w0 == 0x3F800000u) return 2;   // float32
    if (w0 == 0x3F803F80u) return 3;   // bf16
    return 0;                          // int32
}
__device__ __forceinline__ bool mask_at(const void* p, int idx, int mode) {
    switch (mode) {
        case 1:  return ((const unsigned char*)p)[idx] != 0;
        case 2:  return ((const float*)p)[idx] != 0.0f;
        case 3:  return ((const unsigned short*)p)[idx] != 0;
        default: return ((const int*)p)[idx] != 0;
    }
}

// Grid barrier: monotonic ticket counter, no reset needed across graph replays.
// All NBLK blocks co-resident (148 SMs x 4 blocks = 592 >= 512) -> spin is safe.
__device__ __forceinline__ void gbar(unsigned int* ctr) {
    __syncthreads();
    if (threadIdx.x == 0) {
        __threadfence();
        unsigned int ticket = atomicAdd(ctr, 1u);
        unsigned int target = (ticket / NBLK + 1u) * NBLK;
        while (*(volatile unsigned int*)ctr < target) { __nanosleep(32); }
        __threadfence();
    }
    __syncthreads();
}

__global__ void __launch_bounds__(256, 4) k_fused(
    const float* __restrict__ h1, const float* __restrict__ h2,
    const void* __restrict__ sm, const void* __restrict__ am,
    const float* __restrict__ Wq, const float* __restrict__ Wk,
    float* __restrict__ out)
{
    __shared__ __align__(16) float sh[4 * HH];   // 16 KB, reused per phase
    __shared__ float shp[256];                   // partials / q slice
    __shared__ float ziv[NH];

    int bid = blockIdx.x;
    int t = threadIdx.x, warp = t >> 5, lane = t & 31;
    int mode = detect_mode(sm);

    // ======== Phase 1: masked-mean agg + q rows (all 512 blocks, 4 rows each) ========
    // block: b = bid>>8, rows [ (bid&255)*4, +4 ).  warp w: row (w>>1), column half (w&1).
    {
        int b = bid >> 8;
        int og = (bid & 255) * 4;
        if (bid == 0 && t < BB * NH) g_z[t] = 0.f;

        float cnt = 0.f;
#pragma unroll
        for (int a = 0; a < AA; a++) cnt += mask_at(am, b * AA + a, mode) ? 1.f : 0.f;
        float inv = 1.f / fmaxf(cnt, 1.f);
#pragma unroll
        for (int p = 0; p < 4; p++) {
            int i = t + p * 256;
            float s = 0.f;
#pragma unroll
            for (int a = 0; a < AA; a++)
                if (mask_at(am, b * AA + a, mode)) s += h2[(b * AA + a) * HH + i];
            sh[i] = s * inv;
        }
        __syncthreads();

        int r = warp >> 1, half = warp & 1;
        int o = og + r;
        const float4* wrow = (const float4*)(Wq + (size_t)o * HH) + half * 128;
        const float4* ag4 = (const float4*)sh + half * 128;
        float acc = 0.f;
#pragma unroll
        for (int j = 0; j < 4; j++) {
            float4 wv = wrow[lane + j * 32];
            float4 av = ag4[lane + j * 32];
            acc += wv.x * av.x + wv.y * av.y + wv.z * av.z + wv.w * av.w;
        }
#pragma unroll
        for (int off = 16; off; off >>= 1) acc += __shfl_xor_sync(0xffffffffu, acc, off);
        if (lane == 0) shp[warp] = acc;
        __syncthreads();
        if (t < 4) g_q[b * HH + og + t] = shp[2 * t] + shp[2 * t + 1];
        __syncthreads();
    }
    gbar(&g_bar[0]);

    // ======== Phase 2: fold q into Wk -> v (all 512 blocks) ========
    // block: b = bid>>8; h = (bid>>4)&15; cc = bid&15 -> 64 columns.
    // thread (col = t&63, oq = t>>6): partial over 16 o's; smem combine.
    {
        int b = bid >> 8, h = (bid >> 4) & 15, cc = bid & 15;
        if (t < HD) shp[t] = g_q[b * HH + h * HD + t];   // q slice in shp[0..63]
        __syncthreads();
        int col = t & 63, oq = t >> 6;
        int i = cc * 64 + col;
        const float* wkb = Wk + (size_t)(h * HD + oq * 16) * HH + i;
        float acc = 0.f;
#pragma unroll
        for (int o = 0; o < 16; o++)
            acc += shp[oq * 16 + o] * wkb[(size_t)o * HH];
        __syncthreads();
        shp[t] = acc;   // reuse shp as partial grid [oq][col] after q consumed
        __syncthreads();
        if (t < 64)
            g_v[(size_t)(b * NH + h) * HH + cc * 64 + t] =
                shp[t] + shp[64 + t] + shp[128 + t] + shp[192 + t];
        __syncthreads();
    }
    gbar(&g_bar[1]);

    // ======== Phase 3: e = mask ? exp(0.125 * v.h1) : 0 ; atomic z (all 512 blocks) ========
    // block: b = bid>>8; kc = (bid&255)>>2 -> 32 k's; hq = bid&3 -> 4 heads (16KB smem).
    {
        int b = bid >> 8, rem = bid & 255, kc = rem >> 2, hq = rem & 3;
        float4* vs4 = (float4*)sh;
        const float4* vb = (const float4*)(g_v + (size_t)(b * NH + hq * 4) * HH);
#pragma unroll
        for (int j = 0; j < 4; j++) vs4[t + j * 256] = vb[t + j * 256];
        __syncthreads();

        int k0 = kc * 32 + warp * 4;
        const float4* r0 = (const float4*)(h1 + (size_t)(b * SS + k0 + 0) * HH);
        const float4* r1 = (const float4*)(h1 + (size_t)(b * SS + k0 + 1) * HH);
        const float4* r2 = (const float4*)(h1 + (size_t)(b * SS + k0 + 2) * HH);
        const float4* r3 = (const float4*)(h1 + (size_t)(b * SS + k0 + 3) * HH);

        float acc[4][4];
#pragma unroll
        for (int h = 0; h < 4; h++)
#pragma unroll
            for (int j = 0; j < 4; j++) acc[h][j] = 0.f;

#pragma unroll 2
        for (int m = 0; m < 8; m++) {
            int idx = lane + m * 32;
            float4 x0 = __ldcs(r0 + idx), x1 = __ldcs(r1 + idx),
                   x2 = __ldcs(r2 + idx), x3 = __ldcs(r3 + idx);
#pragma unroll
            for (int h = 0; h < 4; h++) {
                float4 v = vs4[h * (HH / 4) + idx];
                acc[h][0] += v.x * x0.x + v.y * x0.y + v.z * x0.z + v.w * x0.w;
                acc[h][1] += v.x * x1.x + v.y * x1.y + v.z * x1.z + v.w * x1.w;
                acc[h][2] += v.x * x2.x + v.y * x2.y + v.z * x2.z + v.w * x2.w;
                acc[h][3] += v.x * x3.x + v.y * x3.y + v.z * x3.z + v.w * x3.w;
            }
        }
#pragma unroll
        for (int h = 0; h < 4; h++)
#pragma unroll
            for (int j = 0; j < 4; j++) {
                float s = acc[h][j];
#pragma unroll
                for (int off = 16; off; off >>= 1) s += __shfl_xor_sync(0xffffffffu, s, off);
                acc[h][j] = s;
            }
        if (lane < 16) {
            int h = lane & 3, j = lane >> 2;
            int k = k0 + j;
            float e = 0.f;
            if (mask_at(sm, b * SS + k, mode)) e = __expf(acc[h][j] * 0.125f);
            g_e[(size_t)(b * NH + hq * 4 + h) * SS + k] = e;
            atomicAdd(&g_z[b * NH + hq * 4 + h], e);
        }
        __syncthreads();
    }
    gbar(&g_bar[2]);

    // ======== Phase 4: column-tiled weights + streaming broadcast (all 512 blocks) ========
    // block: b = bid>>8; cc = (bid>>6)&3 -> 512 cols; rg = bid&63 -> 32 rows.
    {
        int b = bid >> 8, rem = bid & 255;
        int c0 = ((rem >> 6) & 3) * 512;
        int r0 = (rem & 63) * 32;

        if (t < NH) ziv[t] = 1.f / (g_z[b * NH + t] * (float)NH);
        __syncthreads();

#pragma unroll
        for (int p = 0; p < 2; p++) {
            int c = c0 + t + p * 256;
            float wv = 0.f;
#pragma unroll
            for (int h = 0; h < NH; h++)
                wv += __ldcs(&g_e[(size_t)(b * NH + h) * SS + c]) * ziv[h];
            sh[t + p * 256] = wv;
        }
        __syncthreads();

        const float4* s4 = (const float4*)sh;   // 128 float4 = 512 cols
        float4 v0 = s4[lane], v1 = s4[lane + 32], v2 = s4[lane + 64], v3 = s4[lane + 96];
        int rowbase = r0 + warp * 4;
#pragma unroll
        for (int j = 0; j < 4; j++) {
            float4* dst = (float4*)(out + (size_t)(b * SS + rowbase + j) * SS + c0);
            __stcs(dst + lane,      v0);
            __stcs(dst + lane + 32, v1);
            __stcs(dst + lane + 64, v2);
            __stcs(dst + lane + 96, v3);
        }
    }
}

extern "C" void kernel_launch(void* const* d_in, const int* in_sizes, int n_in,
                              void* d_out, int out_size) {
    const float* h1 = (const float*)d_in[0];   // [B,S,H]
    const float* h2 = (const float*)d_in[1];   // [B,A,H]
    const void*  sm = d_in[2];                 // [B,S]
    const void*  am = d_in[3];                 // [B,A]
    const float* Wq = (const float*)d_in[4];   // [H,H]
    const float* Wk = (const float*)d_in[5];   // [H,H]
    float* out = (float*)d_out;                // [B,S,S]

    k_fused<<<NBLK, 256>>>(h1, h2, sm, am, Wq, Wk, out);
}

// round 14
// speedup vs baseline: 1.1709x; 1.1709x over previous
#include <cuda_runtime.h>
#include <cstdint>

// Problem shape (fixed by dataset): B=2, S=2048, A=16, H=1024, NH=16, HD=64
#define BB 2
#define SS 2048
#define AA 16
#define HH 1024
#define NH 16
#define HD 64
#define NBLK 256

// ---- scratch (device globals; no allocation allowed) ----
__device__ __align__(16) float g_q[BB * HH];           // q[b, o]
__device__ __align__(16) float g_v[BB * NH * HH];      // folded key weights v[b, h, i]
__device__ __align__(16) float g_e[BB * NH * SS];      // e[b,h,k] = masked exp(score)
__device__ __align__(16) float g_z[BB * NH];           // per-(b,h) sum of e
__device__ unsigned int g_bar[4];                      // monotonic grid-barrier counters

// ---- mask dtype detection (sentence_mask[0][0..3] always true since len >= S/2) ----
__device__ __forceinline__ int detect_mode(const void* sm) {
    unsigned int w0 = *(const unsigned int*)sm;
    if (w0 == 0x01010101u) return 1;   // 1-byte bool
    if (w0 == 0x3F800000u) return 2;   // float32
    if (w0 == 0x3F803F80u) return 3;   // bf16
    return 0;                          // int32
}
__device__ __forceinline__ bool mask_at(const void* p, int idx, int mode) {
    switch (mode) {
        case 1:  return ((const unsigned char*)p)[idx] != 0;
        case 2:  return ((const float*)p)[idx] != 0.0f;
        case 3:  return ((const unsigned short*)p)[idx] != 0;
        default: return ((const int*)p)[idx] != 0;
    }
}

// P3 work mapping with SM-pairing: classic placement gives smid = LUT[bid % 148],
// so blocks bid and bid+148 share an SM (and its L1). Map them to the SAME
// (b, kc) h1 rows with different head-halves so one 128KB h1 set serves both.
//   bid <  148, pid < 128 : unit = pid,       hh = 0
//   bid <  148, pid >=128 : unit = pid - 20,  hh = 1   (units 108..127)
//   bid >= 148            : unit = bid - 148, hh = 1   (units 0..107)
// unit in [0,128): b = unit>>6, kc = unit&63 (32 k's each).
__device__ __forceinline__ void p3_map(int bid, int& b, int& kc, int& hh) {
    int unit;
    if (bid < 148) {
        if (bid < 128) { unit = bid; hh = 0; }
        else           { unit = bid - 20; hh = 1; }
    } else           { unit = bid - 148; hh = 1; }
    b = unit >> 6;
    kc = unit & 63;
}

// Grid barrier: monotonic ticket counter, volatile-poll (no RMW spin).
// All NBLK blocks co-resident (148 SMs x 2 >= 256) -> spin is safe.
__device__ __forceinline__ void gbar(unsigned int* ctr) {
    __syncthreads();
    if (threadIdx.x == 0) {
        __threadfence();
        unsigned int ticket = atomicAdd(ctr, 1u);
        unsigned int target = (ticket / NBLK + 1u) * NBLK;
        while (*(volatile unsigned int*)ctr < target) { __nanosleep(32); }
        __threadfence();
    }
    __syncthreads();
}

__global__ void __launch_bounds__(256, 2) k_fused(
    const float* __restrict__ h1, const float* __restrict__ h2,
    const void* __restrict__ sm, const void* __restrict__ am,
    const float* __restrict__ Wq, const float* __restrict__ Wk,
    float* __restrict__ out)
{
    __shared__ __align__(16) float sh[8 * HH];   // 32 KB, reused per phase
    __shared__ float shq[HD];
    __shared__ float ziv[NH];

    int bid = blockIdx.x;
    int t = threadIdx.x, warp = t >> 5, lane = t & 31;
    int mode = detect_mode(sm);

    // ======== Phase 1: masked-mean agg + q rows (ALL 256 blocks) ========
    // block: b = bid>>7, rows [ (bid&127)*8, +8 ), one row per warp.
    {
        int b = bid >> 7;
        int og = (bid & 127) * 8;
        if (bid == 0 && t < BB * NH) g_z[t] = 0.f;

        float cnt = 0.f;
#pragma unroll
        for (int a = 0; a < AA; a++) cnt += mask_at(am, b * AA + a, mode) ? 1.f : 0.f;
        float inv = 1.f / fmaxf(cnt, 1.f);
#pragma unroll
        for (int p = 0; p < 4; p++) {
            int i = t + p * 256;
            float s = 0.f;
#pragma unroll
            for (int a = 0; a < AA; a++)
                if (mask_at(am, b * AA + a, mode)) s += h2[(b * AA + a) * HH + i];
            sh[i] = s * inv;
        }
        __syncthreads();

        const float4* ag4 = (const float4*)sh;
        int o = og + warp;
        const float4* wrow = (const float4*)(Wq + (size_t)o * HH);
        float acc = 0.f;
#pragma unroll
        for (int j = 0; j < 8; j++) {
            float4 wv = __ldcs(wrow + lane + j * 32);   // single-use: keep out of L1
            float4 av = ag4[lane + j * 32];
            acc += wv.x * av.x + wv.y * av.y + wv.z * av.z + wv.w * av.w;
        }
#pragma unroll
        for (int off = 16; off; off >>= 1) acc += __shfl_xor_sync(0xffffffffu, acc, off);
        if (lane == 0) g_q[b * HH + o] = acc;
        __syncthreads();
    }
    gbar(&g_bar[0]);

    // ======== Phase 2: fold q -> v (blocks 0..127) + h1 L1-prefetch (ALL blocks) ========
    if (bid < 128) {
        int b = bid >> 6, h = (bid >> 2) & 15, qtr = bid & 3;
        if (t < HD) shq[t] = g_q[b * HH + h * HD + t];
        __syncthreads();
        int i = qtr * 256 + t;
        const float* wkb = Wk + (size_t)(h * HD) * HH;
        float acc = 0.f;
#pragma unroll 8
        for (int o = 0; o < HD; o++)
            acc += __ldcs(wkb + (size_t)o * HH + i) * shq[o];   // single-use stream
        g_v[(size_t)(b * NH + h) * HH + i] = acc;
        __syncthreads();
    }
    // Prefetch this block's Phase-3 h1 working set (32 rows x 4KB = 128KB) into L1.
    // SM-paired blocks (bid, bid+148) prefetch the SAME rows -> one shared set.
    {
        int pb, pkc, phh;
        p3_map(bid, pb, pkc, phh);
        (void)phh;
        const char* base = (const char*)(h1 + (size_t)(pb * SS + pkc * 32) * HH);
#pragma unroll
        for (int j = 0; j < 4; j++) {
            const char* p = base + (size_t)(t + j * 256) * 128;   // 1024 x 128B lines
            asm volatile("prefetch.global.L1 [%0];" :: "l"(p));
        }
    }
    gbar(&g_bar[1]);

    // ======== Phase 3: e = mask ? exp(0.125 * v.h1) : 0 ; atomic z (all blocks) ========
    // SM-paired mapping (see p3_map); 8 heads per block (32KB smem), 8 warps x 4 k.
    // h1 loads are plain (L1-cached, prefetched); v staging uses __ldcs.
    {
        int b, kc, hh;
        p3_map(bid, b, kc, hh);
        float4* vs4 = (float4*)sh;
        const float4* vb = (const float4*)(g_v + (size_t)(b * NH + hh * 8) * HH);
#pragma unroll
        for (int j = 0; j < 8; j++) vs4[t + j * 256] = __ldcs(vb + t + j * 256);
        __syncthreads();

        int k0 = kc * 32 + warp * 4;
        const float4* r0 = (const float4*)(h1 + (size_t)(b * SS + k0 + 0) * HH);
        const float4* r1 = (const float4*)(h1 + (size_t)(b * SS + k0 + 1) * HH);
        const float4* r2 = (const float4*)(h1 + (size_t)(b * SS + k0 + 2) * HH);
        const float4* r3 = (const float4*)(h1 + (size_t)(b * SS + k0 + 3) * HH);

        float acc[8][4];
#pragma unroll
        for (int h = 0; h < 8; h++)
#pragma unroll
            for (int j = 0; j < 4; j++) acc[h][j] = 0.f;

#pragma unroll 2
        for (int m = 0; m < 8; m++) {
            int idx = lane + m * 32;
            float4 x0 = r0[idx], x1 = r1[idx], x2 = r2[idx], x3 = r3[idx];
#pragma unroll
            for (int h = 0; h < 8; h++) {
                float4 v = vs4[h * (HH / 4) + idx];
                acc[h][0] += v.x * x0.x + v.y * x0.y + v.z * x0.z + v.w * x0.w;
                acc[h][1] += v.x * x1.x + v.y * x1.y + v.z * x1.z + v.w * x1.w;
                acc[h][2] += v.x * x2.x + v.y * x2.y + v.z * x2.z + v.w * x2.w;
                acc[h][3] += v.x * x3.x + v.y * x3.y + v.z * x3.z + v.w * x3.w;
            }
        }
#pragma unroll
        for (int h = 0; h < 8; h++)
#pragma unroll
            for (int j = 0; j < 4; j++) {
                float s = acc[h][j];
#pragma unroll
                for (int off = 16; off; off >>= 1) s += __shfl_xor_sync(0xffffffffu, s, off);
                acc[h][j] = s;
            }
        {
            int h = lane & 7, j = lane >> 3;
            int k = k0 + j;
            float e = 0.f;
            if (mask_at(sm, b * SS + k, mode)) e = __expf(acc[h][j] * 0.125f);
            g_e[(size_t)(b * NH + hh * 8 + h) * SS + k] = e;
            atomicAdd(&g_z[b * NH + hh * 8 + h], e);
        }
        __syncthreads();
    }
    gbar(&g_bar[2]);

    // ======== Phase 4: column-tiled weights + streaming broadcast ========
    // block: b = bid>>7; cg = (bid>>5)&3 -> 512 cols; rg = bid&31 -> 64 rows.
    {
        int b = bid >> 7, rem = bid & 127;
        int c0 = (rem >> 5) * 512;
        int r0 = (rem & 31) * 64;

        if (t < NH) ziv[t] = 1.f / (g_z[b * NH + t] * (float)NH);
        __syncthreads();

#pragma unroll
        for (int p = 0; p < 2; p++) {
            int c = c0 + t + p * 256;
            float wv = 0.f;
#pragma unroll
            for (int h = 0; h < NH; h++)
                wv += g_e[(size_t)(b * NH + h) * SS + c] * ziv[h];
            sh[t + p * 256] = wv;
        }
        __syncthreads();

        const float4* s4 = (const float4*)sh;   // 128 float4 = 512 cols
        float4 v0 = s4[lane], v1 = s4[lane + 32], v2 = s4[lane + 64], v3 = s4[lane + 96];
        int rowbase = r0 + warp * 8;
#pragma unroll
        for (int j = 0; j < 8; j++) {
            float4* dst = (float4*)(out + (size_t)(b * SS + rowbase + j) * SS + c0);
            __stcs(dst + lane,      v0);
            __stcs(dst + lane + 32, v1);
            __stcs(dst + lane + 64, v2);
            __stcs(dst + lane + 96, v3);
        }
    }
}

extern "C" void kernel_launch(void* const* d_in, const int* in_sizes, int n_in,
                              void* d_out, int out_size) {
    const float* h1 = (const float*)d_in[0];   // [B,S,H]
    const float* h2 = (const float*)d_in[1];   // [B,A,H]
    const void*  sm = d_in[2];                 // [B,S]
    const void*  am = d_in[3];                 // [B,A]
    const float* Wq = (const float*)d_in[4];   // [H,H]
    const float* Wk = (const float*)d_in[5];   // [H,H]
    float* out = (float*)d_out;                // [B,S,S]

    k_fused<<<NBLK, 256>>>(h1, h2, sm, am, Wq, Wk, out);
}

// round 15
// speedup vs baseline: 1.4091x; 1.2035x over previous
#include <cuda_runtime.h>
#include <cstdint>

// Problem shape (fixed by dataset): B=2, S=2048, A=16, H=1024, NH=16, HD=64
#define BB 2
#define SS 2048
#define AA 16
#define HH 1024
#define NH 16
#define HD 64
#define NBLK 256

// ---- scratch (device globals; no allocation allowed) ----
__device__ __align__(16) float g_q[BB * HH];           // q[b, o]
__device__ __align__(16) float g_v[BB * NH * HH];      // folded key weights v[b, h, i]
__device__ __align__(16) float g_e[BB * NH * SS];      // e[b,h,k] = masked exp(score)
__device__ __align__(16) float g_z[BB * NH];           // per-(b,h) sum of e
__device__ unsigned int g_bar[4];                      // monotonic grid-barrier counters

// ---- mask dtype detection (sentence_mask[0][0..3] always true since len >= S/2) ----
__device__ __forceinline__ int detect_mode(const void* sm) {
    unsigned int w0 = *(const unsigned int*)sm;
    if (w0 == 0x01010101u) return 1;   // 1-byte bool
    if (w0 == 0x3F800000u) return 2;   // float32
    if (w0 == 0x3F803F80u) return 3;   // bf16
    return 0;                          // int32
}
__device__ __forceinline__ bool mask_at(const void* p, int idx, int mode) {
    switch (mode) {
        case 1:  return ((const unsigned char*)p)[idx] != 0;
        case 2:  return ((const float*)p)[idx] != 0.0f;
        case 3:  return ((const unsigned short*)p)[idx] != 0;
        default: return ((const int*)p)[idx] != 0;
    }
}

// Grid barrier: monotonic ticket counter, volatile-poll (no RMW spin).
// All NBLK blocks co-resident (148 SMs x 2 >= 256) -> spin is safe.
__device__ __forceinline__ void gbar(unsigned int* ctr) {
    __syncthreads();
    if (threadIdx.x == 0) {
        __threadfence();
        unsigned int ticket = atomicAdd(ctr, 1u);
        unsigned int target = (ticket / NBLK + 1u) * NBLK;
        while (*(volatile unsigned int*)ctr < target) { __nanosleep(32); }
        __threadfence();
    }
    __syncthreads();
}

__global__ void __launch_bounds__(256, 2) k_fused(
    const float* __restrict__ h1, const float* __restrict__ h2,
    const void* __restrict__ sm, const void* __restrict__ am,
    const float* __restrict__ Wq, const float* __restrict__ Wk,
    float* __restrict__ out)
{
    __shared__ __align__(16) float sh[8 * HH];   // 32 KB, reused per phase
    __shared__ float shq[HD];
    __shared__ float ziv[NH];

    int bid = blockIdx.x;
    int t = threadIdx.x, warp = t >> 5, lane = t & 31;
    int mode = detect_mode(sm);

    // ======== Phase 1: masked-mean agg + q rows (ALL 256 blocks) ========
    // block: b = bid>>7, rows [ (bid&127)*8, +8 ), one row per warp.
    {
        int b = bid >> 7;
        int og = (bid & 127) * 8;
        if (bid == 0 && t < BB * NH) g_z[t] = 0.f;

        float cnt = 0.f;
#pragma unroll
        for (int a = 0; a < AA; a++) cnt += mask_at(am, b * AA + a, mode) ? 1.f : 0.f;
        float inv = 1.f / fmaxf(cnt, 1.f);
#pragma unroll
        for (int p = 0; p < 4; p++) {
            int i = t + p * 256;
            float s = 0.f;
#pragma unroll
            for (int a = 0; a < AA; a++)
                if (mask_at(am, b * AA + a, mode)) s += h2[(b * AA + a) * HH + i];
            sh[i] = s * inv;
        }
        __syncthreads();

        const float4* ag4 = (const float4*)sh;
        int o = og + warp;
        const float4* wrow = (const float4*)(Wq + (size_t)o * HH);
        float acc = 0.f;
#pragma unroll
        for (int j = 0; j < 8; j++) {
            float4 wv = __ldcs(wrow + lane + j * 32);   // single-use stream
            float4 av = ag4[lane + j * 32];
            acc += wv.x * av.x + wv.y * av.y + wv.z * av.z + wv.w * av.w;
        }
#pragma unroll
        for (int off = 16; off; off >>= 1) acc += __shfl_xor_sync(0xffffffffu, acc, off);
        if (lane == 0) g_q[b * HH + o] = acc;
        __syncthreads();
    }
    gbar(&g_bar[0]);

    // ======== Phase 2: fold q into Wk -> v[b,h,:] (blocks 0..127) ========
    // block j: b = j>>6, h = (j>>2)&15, quarter = j&3 (256 columns).
    if (bid < 128) {
        int b = bid >> 6, h = (bid >> 2) & 15, qtr = bid & 3;
        if (t < HD) shq[t] = g_q[b * HH + h * HD + t];
        __syncthreads();
        int i = qtr * 256 + t;
        const float* wkb = Wk + (size_t)(h * HD) * HH;
        float acc = 0.f;
#pragma unroll 8
        for (int o = 0; o < HD; o++)
            acc += __ldcs(wkb + (size_t)o * HH + i) * shq[o];   // single-use stream
        g_v[(size_t)(b * NH + h) * HH + i] = acc;
        __syncthreads();
    }
    gbar(&g_bar[1]);

    // ======== Phase 3: e = mask ? exp(0.125 * v.h1) : 0 ; reduced atomic z ========
    // block: b = bid>>7; kc = (bid&127)>>1 -> 32 k's; hh = bid&1 -> 8 heads (32KB smem).
    {
        int b = bid >> 7, rem = bid & 127, kc = rem >> 1, hh = rem & 1;
        float4* vs4 = (float4*)sh;
        const float4* vb = (const float4*)(g_v + (size_t)(b * NH + hh * 8) * HH);
#pragma unroll
        for (int j = 0; j < 8; j++) vs4[t + j * 256] = vb[t + j * 256];
        __syncthreads();

        int k0 = kc * 32 + warp * 4;
        const float4* r0 = (const float4*)(h1 + (size_t)(b * SS + k0 + 0) * HH);
        const float4* r1 = (const float4*)(h1 + (size_t)(b * SS + k0 + 1) * HH);
        const float4* r2 = (const float4*)(h1 + (size_t)(b * SS + k0 + 2) * HH);
        const float4* r3 = (const float4*)(h1 + (size_t)(b * SS + k0 + 3) * HH);

        float acc[8][4];
#pragma unroll
        for (int h = 0; h < 8; h++)
#pragma unroll
            for (int j = 0; j < 4; j++) acc[h][j] = 0.f;

#pragma unroll 2
        for (int m = 0; m < 8; m++) {
            int idx = lane + m * 32;
            float4 x0 = r0[idx], x1 = r1[idx], x2 = r2[idx], x3 = r3[idx];
#pragma unroll
            for (int h = 0; h < 8; h++) {
                float4 v = vs4[h * (HH / 4) + idx];
                acc[h][0] += v.x * x0.x + v.y * x0.y + v.z * x0.z + v.w * x0.w;
                acc[h][1] += v.x * x1.x + v.y * x1.y + v.z * x1.z + v.w * x1.w;
                acc[h][2] += v.x * x2.x + v.y * x2.y + v.z * x2.z + v.w * x2.w;
                acc[h][3] += v.x * x3.x + v.y * x3.y + v.z * x3.z + v.w * x3.w;
            }
        }
#pragma unroll
        for (int h = 0; h < 8; h++)
#pragma unroll
            for (int j = 0; j < 4; j++) {
                float s = acc[h][j];
#pragma unroll
                for (int off = 16; off; off >>= 1) s += __shfl_xor_sync(0xffffffffu, s, off);
                acc[h][j] = s;
            }
        // 32 lanes = 8 heads x 4 k: store e (streaming; read once from L2 in P4).
        // z: per-warp pre-reduction -> ONE atomicAdd per (warp, head): 8/block
        // instead of 32/block (cuts per-address L2-ALU serialization 4x).
        {
            int h = lane & 7, j = lane >> 3;
            int k = k0 + j;
            float e = 0.f;
            if (mask_at(sm, b * SS + k, mode)) e = __expf(acc[h][j] * 0.125f);
            __stcs(&g_e[(size_t)(b * NH + hh * 8 + h) * SS + k], e);
            // gather this head's 4 j-values into lanes 0..7
            float e1 = __shfl_down_sync(0xffffffffu, e, 8);
            float e2 = __shfl_down_sync(0xffffffffu, e, 16);
            float e3 = __shfl_down_sync(0xffffffffu, e, 24);
            if (lane < 8)
                atomicAdd(&g_z[b * NH + hh * 8 + h], e + e1 + e2 + e3);
        }
        __syncthreads();
    }
    gbar(&g_bar[2]);

    // ======== Phase 4: column-tiled weights + streaming broadcast ========
    // block: b = bid>>7; cg = (bid>>5)&3 -> 512 cols; rg = bid&31 -> 64 rows.
    {
        int b = bid >> 7, rem = bid & 127;
        int c0 = (rem >> 5) * 512;
        int r0 = (rem & 31) * 64;

        if (t < NH) ziv[t] = 1.f / (g_z[b * NH + t] * (float)NH);
        __syncthreads();

#pragma unroll
        for (int p = 0; p < 2; p++) {
            int c = c0 + t + p * 256;
            float wv = 0.f;
#pragma unroll
            for (int h = 0; h < NH; h++)
                wv += __ldcs(&g_e[(size_t)(b * NH + h) * SS + c]) * ziv[h];
            sh[t + p * 256] = wv;
        }
        __syncthreads();

        const float4* s4 = (const float4*)sh;   // 128 float4 = 512 cols
        float4 v0 = s4[lane], v1 = s4[lane + 32], v2 = s4[lane + 64], v3 = s4[lane + 96];
        int rowbase = r0 + warp * 8;
#pragma unroll
        for (int j = 0; j < 8; j++) {
            float4* dst = (float4*)(out + (size_t)(b * SS + rowbase + j) * SS + c0);
            __stcs(dst + lane,      v0);
            __stcs(dst + lane + 32, v1);
            __stcs(dst + lane + 64, v2);
            __stcs(dst + lane + 96, v3);
        }
    }
}

extern "C" void kernel_launch(void* const* d_in, const int* in_sizes, int n_in,
                              void* d_out, int out_size) {
    const float* h1 = (const float*)d_in[0];   // [B,S,H]
    const float* h2 = (const float*)d_in[1];   // [B,A,H]
    const void*  sm = d_in[2];                 // [B,S]
    const void*  am = d_in[3];                 // [B,A]
    const float* Wq = (const float*)d_in[4];   // [H,H]
    const float* Wk = (const float*)d_in[5];   // [H,H]
    float* out = (float*)d_out;                // [B,S,S]

    k_fused<<<NBLK, 256>>>(h1, h2, sm, am, Wq, Wk, out);
}

// round 16
// speedup vs baseline: 1.4405x; 1.0222x over previous
#include <cuda_runtime.h>
#include <cstdint>

// Problem shape (fixed by dataset): B=2, S=2048, A=16, H=1024, NH=16, HD=64
#define BB 2
#define SS 2048
#define AA 16
#define HH 1024
#define NH 16
#define HD 64
#define NBLK 256

// ---- scratch (device globals; no allocation allowed) ----
__device__ __align__(16) float g_q[BB * HH];            // q[b, o]
__device__ __align__(16) float g_v[BB * NH * HH];       // folded key weights v[b, h, i]
__device__ __align__(16) float g_e[BB * NH * SS];       // e[b,h,k] = masked exp(score)
__device__ __align__(16) float g_zp[BB * NH * 64];      // per-(b,h) partial z sums, one per kc
__device__ unsigned int g_bar[4];                       // monotonic grid-barrier counters

// ---- mask dtype detection (sentence_mask[0][0..3] always true since len >= S/2) ----
__device__ __forceinline__ int detect_mode(const void* sm) {
    unsigned int w0 = *(const unsigned int*)sm;
    if (w0 == 0x01010101u) return 1;   // 1-byte bool
    if (w0 == 0x3F800000u) return 2;   // float32
    if (w0 == 0x3F803F80u) return 3;   // bf16
    return 0;                          // int32
}
__device__ __forceinline__ bool mask_at(const void* p, int idx, int mode) {
    switch (mode) {
        case 1:  return ((const unsigned char*)p)[idx] != 0;
        case 2:  return ((const float*)p)[idx] != 0.0f;
        case 3:  return ((const unsigned short*)p)[idx] != 0;
        default: return ((const int*)p)[idx] != 0;
    }
}

// Grid barrier: monotonic ticket counter, volatile-poll (no RMW spin).
// All NBLK blocks co-resident (148 SMs x 2 >= 256) -> spin is safe.
__device__ __forceinline__ void gbar(unsigned int* ctr) {
    __syncthreads();
    if (threadIdx.x == 0) {
        __threadfence();
        unsigned int ticket = atomicAdd(ctr, 1u);
        unsigned int target = (ticket / NBLK + 1u) * NBLK;
        while (*(volatile unsigned int*)ctr < target) { __nanosleep(32); }
        __threadfence();
    }
    __syncthreads();
}

__global__ void __launch_bounds__(256, 2) k_fused(
    const float* __restrict__ h1, const float* __restrict__ h2,
    const void* __restrict__ sm, const void* __restrict__ am,
    const float* __restrict__ Wq, const float* __restrict__ Wk,
    float* __restrict__ out)
{
    __shared__ __align__(16) float sh[8 * HH];   // 32 KB, reused per phase
    __shared__ float shq[HD];
    __shared__ float shz[8];                     // per-head block partial z
    __shared__ float ziv[NH];

    int bid = blockIdx.x;
    int t = threadIdx.x, warp = t >> 5, lane = t & 31;
    int mode = detect_mode(sm);

    // ======== Phase 1: masked-mean agg + q rows (ALL 256 blocks) ========
    // block: b = bid>>7, rows [ (bid&127)*8, +8 ), one row per warp.
    {
        int b = bid >> 7;
        int og = (bid & 127) * 8;

        float cnt = 0.f;
#pragma unroll
        for (int a = 0; a < AA; a++) cnt += mask_at(am, b * AA + a, mode) ? 1.f : 0.f;
        float inv = 1.f / fmaxf(cnt, 1.f);
#pragma unroll
        for (int p = 0; p < 4; p++) {
            int i = t + p * 256;
            float s = 0.f;
#pragma unroll
            for (int a = 0; a < AA; a++)
                if (mask_at(am, b * AA + a, mode)) s += h2[(b * AA + a) * HH + i];
            sh[i] = s * inv;
        }
        __syncthreads();

        const float4* ag4 = (const float4*)sh;
        int o = og + warp;
        const float4* wrow = (const float4*)(Wq + (size_t)o * HH);
        float acc = 0.f;
#pragma unroll
        for (int j = 0; j < 8; j++) {
            float4 wv = __ldcs(wrow + lane + j * 32);   // single-use stream
            float4 av = ag4[lane + j * 32];
            acc += wv.x * av.x + wv.y * av.y + wv.z * av.z + wv.w * av.w;
        }
#pragma unroll
        for (int off = 16; off; off >>= 1) acc += __shfl_xor_sync(0xffffffffu, acc, off);
        if (lane == 0) g_q[b * HH + o] = acc;
        __syncthreads();
    }
    gbar(&g_bar[0]);

    // ======== Phase 2: fold q into Wk -> v[b,h,:] (blocks 0..127) ========
    // block j: b = j>>6, h = (j>>2)&15, quarter = j&3 (256 columns).
    if (bid < 128) {
        int b = bid >> 6, h = (bid >> 2) & 15, qtr = bid & 3;
        if (t < HD) shq[t] = g_q[b * HH + h * HD + t];
        __syncthreads();
        int i = qtr * 256 + t;
        const float* wkb = Wk + (size_t)(h * HD) * HH;
        float acc = 0.f;
#pragma unroll 8
        for (int o = 0; o < HD; o++)
            acc += __ldcs(wkb + (size_t)o * HH + i) * shq[o];   // single-use stream
        g_v[(size_t)(b * NH + h) * HH + i] = acc;
        __syncthreads();
    }
    gbar(&g_bar[1]);

    // ======== Phase 3: e = mask ? exp(0.125 * v.h1) : 0 ; contention-free z ========
    // block: b = bid>>7; kc = (bid&127)>>1 -> 32 k's; hh = bid&1 -> 8 heads (32KB smem).
    // z path: warp head-sums -> smem atomic (on-SM) -> ONE plain STG per (block,head)
    // to a distinct g_zp slot. Zero global atomic contention; fully deterministic.
    {
        int b = bid >> 7, rem = bid & 127, kc = rem >> 1, hh = rem & 1;
        if (t < 8) shz[t] = 0.f;
        float4* vs4 = (float4*)sh;
        const float4* vb = (const float4*)(g_v + (size_t)(b * NH + hh * 8) * HH);
#pragma unroll
        for (int j = 0; j < 8; j++) vs4[t + j * 256] = vb[t + j * 256];
        __syncthreads();

        int k0 = kc * 32 + warp * 4;
        const float4* r0 = (const float4*)(h1 + (size_t)(b * SS + k0 + 0) * HH);
        const float4* r1 = (const float4*)(h1 + (size_t)(b * SS + k0 + 1) * HH);
        const float4* r2 = (const float4*)(h1 + (size_t)(b * SS + k0 + 2) * HH);
        const float4* r3 = (const float4*)(h1 + (size_t)(b * SS + k0 + 3) * HH);

        float acc[8][4];
#pragma unroll
        for (int h = 0; h < 8; h++)
#pragma unroll
            for (int j = 0; j < 4; j++) acc[h][j] = 0.f;

#pragma unroll 2
        for (int m = 0; m < 8; m++) {
            int idx = lane + m * 32;
            float4 x0 = r0[idx], x1 = r1[idx], x2 = r2[idx], x3 = r3[idx];
#pragma unroll
            for (int h = 0; h < 8; h++) {
                float4 v = vs4[h * (HH / 4) + idx];
                acc[h][0] += v.x * x0.x + v.y * x0.y + v.z * x0.z + v.w * x0.w;
                acc[h][1] += v.x * x1.x + v.y * x1.y + v.z * x1.z + v.w * x1.w;
                acc[h][2] += v.x * x2.x + v.y * x2.y + v.z * x2.z + v.w * x2.w;
                acc[h][3] += v.x * x3.x + v.y * x3.y + v.z * x3.z + v.w * x3.w;
            }
        }
#pragma unroll
        for (int h = 0; h < 8; h++)
#pragma unroll
            for (int j = 0; j < 4; j++) {
                float s = acc[h][j];
#pragma unroll
                for (int off = 16; off; off >>= 1) s += __shfl_xor_sync(0xffffffffu, s, off);
                acc[h][j] = s;
            }
        // 32 lanes = 8 heads x 4 k: store e (streaming; read once from L2 in P4).
        {
            int h = lane & 7, j = lane >> 3;
            int k = k0 + j;
            float e = 0.f;
            if (mask_at(sm, b * SS + k, mode)) e = __expf(acc[h][j] * 0.125f);
            __stcs(&g_e[(size_t)(b * NH + hh * 8 + h) * SS + k], e);
            // head-sum of this warp's 4 k's -> lanes 0..7
            float e1 = __shfl_down_sync(0xffffffffu, e, 8);
            float e2 = __shfl_down_sync(0xffffffffu, e, 16);
            float e3 = __shfl_down_sync(0xffffffffu, e, 24);
            if (lane < 8) atomicAdd(&shz[lane], e + e1 + e2 + e3);   // on-SM ATOMS
        }
        __syncthreads();
        if (t < 8)
            g_zp[(size_t)(b * NH + hh * 8 + t) * 64 + kc] = shz[t]; // distinct slot
        __syncthreads();
    }
    gbar(&g_bar[2]);

    // ======== Phase 4: z from partials + column-tiled weights + broadcast ========
    // block: b = bid>>7; cg = (bid>>5)&3 -> 512 cols; rg = bid&31 -> 64 rows.
    {
        int b = bid >> 7, rem = bid & 127;
        int c0 = (rem >> 5) * 512;
        int r0 = (rem & 31) * 64;

        // z[b,h] = sum of 64 partials; 8 threads per head, width-8 shuffle combine.
        if (t < 128) {
            int h = t >> 3, part = t & 7;
            const float* zp = g_zp + (size_t)(b * NH + h) * 64 + part * 8;
            float s = 0.f;
#pragma unroll
            for (int j = 0; j < 8; j++) s += zp[j];
            s += __shfl_down_sync(0xffffffffu, s, 4, 8);
            s += __shfl_down_sync(0xffffffffu, s, 2, 8);
            s += __shfl_down_sync(0xffffffffu, s, 1, 8);
            if (part == 0) ziv[h] = 1.f / (s * (float)NH);
        }
        __syncthreads();

#pragma unroll
        for (int p = 0; p < 2; p++) {
            int c = c0 + t + p * 256;
            float wv = 0.f;
#pragma unroll
            for (int h = 0; h < NH; h++)
                wv += __ldcs(&g_e[(size_t)(b * NH + h) * SS + c]) * ziv[h];
            sh[t + p * 256] = wv;
        }
        __syncthreads();

        const float4* s4 = (const float4*)sh;   // 128 float4 = 512 cols
        float4 v0 = s4[lane], v1 = s4[lane + 32], v2 = s4[lane + 64], v3 = s4[lane + 96];
        int rowbase = r0 + warp * 8;
#pragma unroll
        for (int j = 0; j < 8; j++) {
            float4* dst = (float4*)(out + (size_t)(b * SS + rowbase + j) * SS + c0);
            __stcs(dst + lane,      v0);
            __stcs(dst + lane + 32, v1);
            __stcs(dst + lane + 64, v2);
            __stcs(dst + lane + 96, v3);
        }
    }
}

extern "C" void kernel_launch(void* const* d_in, const int* in_sizes, int n_in,
                              void* d_out, int out_size) {
    const float* h1 = (const float*)d_in[0];   // [B,S,H]
    const float* h2 = (const float*)d_in[1];   // [B,A,H]
    const void*  sm = d_in[2];                 // [B,S]
    const void*  am = d_in[3];                 // [B,A]
    const float* Wq = (const float*)d_in[4];   // [H,H]
    const float* Wk = (const float*)d_in[5];   // [H,H]
    float* out = (float*)d_out;                // [B,S,S]

    k_fused<<<NBLK, 256>>>(h1, h2, sm, am, Wq, Wk, out);
}